// round 8
// baseline (speedup 1.0000x reference)
#include <cuda_runtime.h>
#include <math.h>

#define BATCH 4096
#define DIM 1024
#define NG 1024
#define NSPLIT 64            // column splits of 64 (per warp-column)
#define TEMP_INV 10.0f

// ---------------- scratch ----------------------------------------------------
__device__ __align__(16) signed char g_qh[BATCH * DIM];
__device__ __align__(16) signed char g_ql[BATCH * DIM];
__device__ __align__(16) signed char g_ah[BATCH * DIM];
__device__ __align__(16) signed char g_al[BATCH * DIM];
__device__ float  g_sq[BATCH];
__device__ float  g_sa[BATCH];

__device__ int    g_smax[NG];
__device__ int    g_smin[NG];
__device__ float  g_wsum[NG];
__device__ float  g_w[BATCH];
__device__ float  g_pm[BATCH * NSPLIT];
__device__ float  g_ps[BATCH * NSPLIT];
__device__ float  g_pmaxv[BATCH * NSPLIT];
__device__ int    g_pmaxj[BATCH * NSPLIT];
__device__ float  g_pdot[BATCH * NSPLIT];
__device__ float  g_pwr[BATCH * NSPLIT];
__device__ double g_loss;
__device__ int    g_acc;

// ---------------- PTX helpers -------------------------------------------------
__device__ __forceinline__ unsigned smem_u32(const void* p) {
    unsigned a;
    asm("{ .reg .u64 t; cvta.to.shared.u64 t, %1; cvt.u32.u64 %0, t; }" : "=r"(a) : "l"(p));
    return a;
}

__device__ __forceinline__ void cp16(unsigned dst, const void* src) {
    asm volatile("cp.async.cg.shared.global [%0], [%1], 16;" :: "r"(dst), "l"(src) : "memory");
}
__device__ __forceinline__ void cp_commit() {
    asm volatile("cp.async.commit_group;" ::: "memory");
}
template <int N>
__device__ __forceinline__ void cp_wait() {
    asm volatile("cp.async.wait_group %0;" :: "n"(N) : "memory");
}

__device__ __forceinline__ void ldsm4(unsigned& r0, unsigned& r1, unsigned& r2, unsigned& r3,
                                      unsigned addr) {
    asm volatile("ldmatrix.sync.aligned.m8n8.x4.shared.b16 {%0,%1,%2,%3}, [%4];"
        : "=r"(r0), "=r"(r1), "=r"(r2), "=r"(r3) : "r"(addr));
}

__device__ __forceinline__ void mma_s8(int* c, unsigned a0, unsigned a1, unsigned a2,
                                       unsigned a3, unsigned b0, unsigned b1) {
    asm volatile(
        "mma.sync.aligned.m16n8k32.row.col.s32.s8.s8.s32 "
        "{%0,%1,%2,%3}, {%4,%5,%6,%7}, {%8,%9}, {%0,%1,%2,%3};"
        : "+r"(c[0]), "+r"(c[1]), "+r"(c[2]), "+r"(c[3])
        : "r"(a0), "r"(a1), "r"(a2), "r"(a3), "r"(b0), "r"(b1));
}

// ---------------- weight prep -------------------------------------------------
__global__ void k_init() {
    int i = blockIdx.x * blockDim.x + threadIdx.x;
    if (i < NG) {
        g_smax[i] = 0xFF800000;
        g_smin[i] = 0x7F800000;
        g_wsum[i] = 0.0f;
    }
    if (i == 0) { g_loss = 0.0; g_acc = 0; }
}

__global__ void k_minmax(const float* __restrict__ scores, const int* __restrict__ qid) {
    int i = blockIdx.x * blockDim.x + threadIdx.x;
    if (i >= BATCH) return;
    int b = __float_as_int(scores[i]);
    int g = qid[i];
    atomicMax(&g_smax[g], b);
    atomicMin(&g_smin[g], b);
}

__global__ void k_weight(const float* __restrict__ scores, const float* __restrict__ ranks,
                         const int* __restrict__ qid) {
    int i = blockIdx.x * blockDim.x + threadIdx.x;
    if (i >= BATCH) return;
    int g = qid[i];
    float w = expf(-0.1f * ranks[i]);
    float mx = __int_as_float(g_smax[g]);
    float mn = __int_as_float(g_smin[g]);
    float den = mx - mn;
    float norm = (den > 0.0f) ? (scores[i] - mn) / den : 0.0f;
    w *= expf(0.01f * norm);
    g_w[i] = w;
    atomicAdd(&g_wsum[g], w);
}

__global__ void k_wnorm(const int* __restrict__ qid) {
    int i = blockIdx.x * blockDim.x + threadIdx.x;
    if (i >= BATCH) return;
    g_w[i] = g_w[i] / g_wsum[qid[i]];
}

// ---------------- fp32 -> int8 hi/lo with per-row scale ----------------------
// v ~= s*(h + l/128), s = maxabs/127, |h|<=127, |l|<=64, err <= maxabs/32512.
__global__ void __launch_bounds__(256) k_quant(const float* __restrict__ Q,
                                               const float* __restrict__ A) {
    __shared__ float red[8];
    const int row = blockIdx.x;
    const int isQ = (blockIdx.y == 0);
    const float* src = (isQ ? Q : A) + (size_t)row * DIM;
    const int tid = threadIdx.x;

    float4 f = *(const float4*)(src + tid * 4);
    float mx = fmaxf(fmaxf(fabsf(f.x), fabsf(f.y)), fmaxf(fabsf(f.z), fabsf(f.w)));
#pragma unroll
    for (int off = 16; off > 0; off >>= 1)
        mx = fmaxf(mx, __shfl_xor_sync(0xffffffffu, mx, off));
    if ((tid & 31) == 0) red[tid >> 5] = mx;
    __syncthreads();
    if (tid == 0) {
        float m2 = red[0];
#pragma unroll
        for (int i = 1; i < 8; i++) m2 = fmaxf(m2, red[i]);
        red[0] = m2;
        (isQ ? g_sq : g_sa)[row] = m2 * (1.0f / 127.0f);
    }
    __syncthreads();
    float mall = red[0];
    float s = mall * (1.0f / 127.0f);
    float inv = 127.0f / mall;

    float v[4] = {f.x, f.y, f.z, f.w};
    char hc[4], lc[4];
#pragma unroll
    for (int i = 0; i < 4; i++) {
        float h = rintf(v[i] * inv);
        float l = rintf((v[i] - h * s) * inv * 128.0f);
        hc[i] = (char)(int)h;
        lc[i] = (char)(int)l;
    }
    size_t off = (size_t)row * DIM + tid * 4;
    *(char4*)((isQ ? g_qh : g_ah) + off) = make_char4(hc[0], hc[1], hc[2], hc[3]);
    *(char4*)((isQ ? g_ql : g_al) + off) = make_char4(lc[0], lc[1], lc[2], lc[3]);
}

// ---------------- main: int8-split mma.sync GEMM + fused epilogue ------------
// Grid (32, 32): CTA tile rows [bx*128,+128) x cols [by*128,+128).
// 8 warps as 4(m) x 2(n); warp tile 32 x 64. K-chunk = 32 (one k32 mma step).
// smem: sq int[128]@0, sw float[128]@512, sa float[128]@1024,
//       stages @2048: 4 x (4 tiles x 6144B)   [tile row stride 48B: 32 data+16 pad]
#define TILE_B  6144u
#define STG_OFF 2048u
#define STG_SZ  (4u * TILE_B)     // 24576
#define NSTAGE  4
#define SMEM_TOTAL (2048 + NSTAGE * 24576)

__global__ void __launch_bounds__(256) k_mma(const int* __restrict__ qid) {
    extern __shared__ char smem[];
    const unsigned sb = smem_u32(smem);
    const int tid = threadIdx.x;
    const int wid = tid >> 5;
    const int lid = tid & 31;
    const int wm = wid & 3;        // m warp 0..3
    const int wn = wid >> 2;       // n warp 0..1
    const int bx = blockIdx.x, by = blockIdx.y;

    // column tables
    if (tid < 128) {
        int c = by * 128 + tid;
        ((int*)(smem))[tid] = qid[c];
        ((float*)(smem + 512))[tid] = g_w[c];
        ((float*)(smem + 1024))[tid] = g_sa[c];
    }

    int accHH[2][8][4], accC[2][8][4];
#pragma unroll
    for (int i = 0; i < 2; i++)
#pragma unroll
        for (int j = 0; j < 8; j++)
#pragma unroll
            for (int k = 0; k < 4; k++) { accHH[i][j][k] = 0; accC[i][j][k] = 0; }

    // ---- async load of one k-chunk (K=32) into stage buf --------------------
    auto load_chunk = [&](int kc) {
        if (kc < 32) {
            unsigned stg = sb + STG_OFF + (unsigned)(kc & (NSTAGE - 1)) * STG_SZ;
#pragma unroll
            for (int i = 0; i < 4; i++) {
                int c = tid + i * 256;            // 0..1023
                int tile = c >> 8;                // 0 qh, 1 ql, 2 ah, 3 al
                int ci = c & 255;
                int row = ci >> 1;
                int half = ci & 1;
                const signed char* base =
                    (tile == 0) ? g_qh : (tile == 1) ? g_ql : (tile == 2) ? g_ah : g_al;
                int grow = ((tile < 2) ? bx : by) * 128 + row;
                const signed char* src = base + (size_t)grow * DIM + kc * 32 + half * 16;
                unsigned dst = stg + tile * TILE_B + row * 48 + half * 16;
                cp16(dst, src);
            }
        }
        cp_commit();   // constant group count, even past the end
    };

    // ldmatrix lane-address components
    // A (m16 x k32): matrices = (rows0-7,b0-15),(rows8-15,b0-15),(rows0-7,b16-31),(rows8-15,b16-31)
    const int a_row = (((lid >> 3) & 1) << 3) + (lid & 7);
    const int a_byte = (lid >> 4) << 4;
    // B (n16 x k32): matrices = (cols0-7,b0-15),(cols0-7,b16-31),(cols8-15,b0-15),(cols8-15,b16-31)
    const int b_row = ((lid >> 4) << 3) + (lid & 7);
    const int b_byte = ((lid >> 3) & 1) << 4;

    load_chunk(0);
    load_chunk(1);
    load_chunk(2);

    for (int kc = 0; kc < 32; kc++) {
        cp_wait<2>();         // chunk kc's stores complete (kc+1, kc+2 may pend)
        __syncthreads();      // visibility of chunk kc; frees buf (kc+3)%4
        load_chunk(kc + 3);   // prefetch 3 ahead (empty commit past end)

        unsigned stg = sb + STG_OFF + (unsigned)(kc & (NSTAGE - 1)) * STG_SZ;
        unsigned qhb = stg + 0 * TILE_B;
        unsigned qlb = stg + 1 * TILE_B;
        unsigned ahb = stg + 2 * TILE_B;
        unsigned alb = stg + 3 * TILE_B;

        unsigned aH[2][4], aL[2][4];
#pragma unroll
        for (int mt = 0; mt < 2; mt++) {
            unsigned ad = qhb + (wm * 32 + mt * 16 + a_row) * 48 + a_byte;
            ldsm4(aH[mt][0], aH[mt][1], aH[mt][2], aH[mt][3], ad);
            unsigned ad2 = qlb + (wm * 32 + mt * 16 + a_row) * 48 + a_byte;
            ldsm4(aL[mt][0], aL[mt][1], aL[mt][2], aL[mt][3], ad2);
        }

#pragma unroll
        for (int nb = 0; nb < 2; nb++) {          // two n32 halves
            unsigned bh[2][4], bl[2][4];
#pragma unroll
            for (int p2 = 0; p2 < 2; p2++) {      // n16 tiles
                int ncol = wn * 64 + nb * 32 + p2 * 16;
                unsigned bd = ahb + (ncol + b_row) * 48 + b_byte;
                ldsm4(bh[p2][0], bh[p2][1], bh[p2][2], bh[p2][3], bd);
                unsigned bd2 = alb + (ncol + b_row) * 48 + b_byte;
                ldsm4(bl[p2][0], bl[p2][1], bl[p2][2], bl[p2][3], bd2);
            }
#pragma unroll
            for (int mt = 0; mt < 2; mt++)
#pragma unroll
                for (int p2 = 0; p2 < 2; p2++)
#pragma unroll
                    for (int nn = 0; nn < 2; nn++) {
                        int nt = nb * 4 + p2 * 2 + nn;
                        unsigned h0 = bh[p2][2 * nn], h1 = bh[p2][2 * nn + 1];
                        unsigned l0 = bl[p2][2 * nn], l1 = bl[p2][2 * nn + 1];
                        mma_s8(accHH[mt][nt], aH[mt][0], aH[mt][1], aH[mt][2], aH[mt][3], h0, h1);
                        mma_s8(accC[mt][nt],  aH[mt][0], aH[mt][1], aH[mt][2], aH[mt][3], l0, l1);
                        mma_s8(accC[mt][nt],  aL[mt][0], aL[mt][1], aL[mt][2], aL[mt][3], h0, h1);
                    }
        }
    }

    // ---- fused epilogue -----------------------------------------------------
    const int* sq = (const int*)(smem);
    const float* swt = (const float*)(smem + 512);
    const float* sat = (const float*)(smem + 1024);
    const unsigned fullm = 0xffffffffu;

#pragma unroll
    for (int mt = 0; mt < 2; mt++) {
#pragma unroll
        for (int h = 0; h < 2; h++) {
            int row = bx * 128 + wm * 32 + mt * 16 + h * 8 + (lid >> 2);
            int rq = qid[row];
            float fr = g_sq[row] * TEMP_INV;
            float m = -1e30f, s = 0.0f, mv = -1e30f, dot = 0.0f, wr = 0.0f;
            int mj = 0;
#pragma unroll
            for (int nt = 0; nt < 8; nt++) {
#pragma unroll
                for (int b = 0; b < 2; b++) {
                    int cl = wn * 64 + nt * 8 + 2 * (lid & 3) + b;
                    float val = fr * sat[cl] *
                        ((float)accHH[mt][nt][2 * h + b] +
                         (float)accC[mt][nt][2 * h + b] * 0.0078125f);
                    if (val > m) {
                        s = s * __expf(m - val) + 1.0f;
                        m = val;
                    } else {
                        s += __expf(val - m);
                    }
                    if (val > mv) { mv = val; mj = by * 128 + cl; }
                    if (sq[cl] == rq) {
                        float wj = swt[cl];
                        dot = fmaf(wj, val, dot);
                        wr += wj;
                    }
                }
            }
            // reduce across the 4 lanes owning this row (lanes 4k..4k+3)
#pragma unroll
            for (int off = 2; off > 0; off >>= 1) {
                float om  = __shfl_down_sync(fullm, m, off, 4);
                float os  = __shfl_down_sync(fullm, s, off, 4);
                float omv = __shfl_down_sync(fullm, mv, off, 4);
                int   oj  = __shfl_down_sync(fullm, mj, off, 4);
                float od  = __shfl_down_sync(fullm, dot, off, 4);
                float ow  = __shfl_down_sync(fullm, wr, off, 4);
                float M = fmaxf(m, om);
                s = s * __expf(m - M) + os * __expf(om - M);
                m = M;
                if (omv > mv || (omv == mv && oj < mj)) { mv = omv; mj = oj; }
                dot += od;
                wr += ow;
            }
            if ((lid & 3) == 0) {
                int pidx = row * NSPLIT + (by * 2 + wn);
                g_pm[pidx] = m; g_ps[pidx] = s;
                g_pmaxv[pidx] = mv; g_pmaxj[pidx] = mj;
                g_pdot[pidx] = dot; g_pwr[pidx] = wr;
            }
        }
    }
}

// ---------------- merge splits ------------------------------------------------
__global__ void k_merge(const int* __restrict__ qid) {
    int row = blockIdx.x * blockDim.x + threadIdx.x;
    if (row >= BATCH) return;
    float m = -1e30f, s = 0.0f, mv = -1e30f, dot = 0.0f, wr = 0.0f;
    int mj = 0;
    for (int p = 0; p < NSPLIT; p++) {
        int idx = row * NSPLIT + p;
        float om = g_pm[idx], os = g_ps[idx];
        float M = fmaxf(m, om);
        s = s * __expf(m - M) + os * __expf(om - M);
        m = M;
        float omv = g_pmaxv[idx];
        int oj = g_pmaxj[idx];
        if (omv > mv || (omv == mv && oj < mj)) { mv = omv; mj = oj; }
        dot += g_pdot[idx];
        wr += g_pwr[idx];
    }
    float lse = m + logf(s);
    float per_row = wr * lse - dot;
    int ok = (qid[mj] == qid[row]) ? 1 : 0;
    atomicAdd(&g_loss, (double)per_row);
    atomicAdd(&g_acc, ok);
}

__global__ void k_final(float* __restrict__ out, int out_size) {
    if (threadIdx.x == 0) {
        if (out_size > 0) out[0] = (float)(g_loss / (double)BATCH);
        if (out_size > 1) out[1] = (float)g_acc / (float)BATCH;
    }
}

// ---------------- launch -------------------------------------------------------
extern "C" void kernel_launch(void* const* d_in, const int* in_sizes, int n_in,
                              void* d_out, int out_size) {
    const float* Q      = (const float*)d_in[0];
    const float* A      = (const float*)d_in[1];
    const int*   qid    = (const int*)d_in[2];
    const float* ranks  = (const float*)d_in[3];
    const float* scores = (const float*)d_in[4];
    float* out = (float*)d_out;

    cudaFuncSetAttribute(k_mma, cudaFuncAttributeMaxDynamicSharedMemorySize, SMEM_TOTAL);

    k_init<<<(NG + 255) / 256, 256>>>();
    k_minmax<<<(BATCH + 255) / 256, 256>>>(scores, qid);
    k_weight<<<(BATCH + 255) / 256, 256>>>(scores, ranks, qid);
    k_wnorm<<<(BATCH + 255) / 256, 256>>>(qid);
    k_quant<<<dim3(BATCH, 2), 256>>>(Q, A);
    k_mma<<<dim3(32, 32), 256, SMEM_TOTAL>>>(qid);
    k_merge<<<(BATCH + 255) / 256, 256>>>(qid);
    k_final<<<1, 32>>>(out, out_size);
}

// round 9
// speedup vs baseline: 4.2149x; 4.2149x over previous
#include <cuda_runtime.h>
#include <cuda_fp16.h>
#include <math.h>

#define BATCH 4096
#define DIM 1024
#define NG 1024
#define NSPLIT 64            // column splits of 64 (per warp-column)
#define TEMP_INV 10.0f

// ---------------- scratch ----------------------------------------------------
__device__ __align__(16) unsigned short g_qh[BATCH * DIM];
__device__ __align__(16) unsigned short g_ah[BATCH * DIM];

__device__ int    g_smax[NG];
__device__ int    g_smin[NG];
__device__ float  g_wsum[NG];
__device__ float  g_w[BATCH];
__device__ float  g_pm[BATCH * NSPLIT];
__device__ float  g_ps[BATCH * NSPLIT];
__device__ float  g_pmaxv[BATCH * NSPLIT];
__device__ int    g_pmaxj[BATCH * NSPLIT];
__device__ float  g_pdot[BATCH * NSPLIT];
__device__ float  g_pwr[BATCH * NSPLIT];
__device__ double g_loss;
__device__ int    g_acc;

// ---------------- PTX helpers -------------------------------------------------
__device__ __forceinline__ unsigned smem_u32(const void* p) {
    unsigned a;
    asm("{ .reg .u64 t; cvta.to.shared.u64 t, %1; cvt.u32.u64 %0, t; }" : "=r"(a) : "l"(p));
    return a;
}

__device__ __forceinline__ void cp16(unsigned dst, const void* src) {
    asm volatile("cp.async.cg.shared.global [%0], [%1], 16;" :: "r"(dst), "l"(src) : "memory");
}
__device__ __forceinline__ void cp_commit() {
    asm volatile("cp.async.commit_group;" ::: "memory");
}
template <int N>
__device__ __forceinline__ void cp_wait() {
    asm volatile("cp.async.wait_group %0;" :: "n"(N) : "memory");
}

__device__ __forceinline__ void ldsm4(unsigned& r0, unsigned& r1, unsigned& r2, unsigned& r3,
                                      unsigned addr) {
    asm volatile("ldmatrix.sync.aligned.m8n8.x4.shared.b16 {%0,%1,%2,%3}, [%4];"
        : "=r"(r0), "=r"(r1), "=r"(r2), "=r"(r3) : "r"(addr));
}

__device__ __forceinline__ void mma_f16(float* c, unsigned a0, unsigned a1, unsigned a2,
                                        unsigned a3, unsigned b0, unsigned b1) {
    asm volatile(
        "mma.sync.aligned.m16n8k16.row.col.f32.f16.f16.f32 "
        "{%0,%1,%2,%3}, {%4,%5,%6,%7}, {%8,%9}, {%0,%1,%2,%3};"
        : "+f"(c[0]), "+f"(c[1]), "+f"(c[2]), "+f"(c[3])
        : "r"(a0), "r"(a1), "r"(a2), "r"(a3), "r"(b0), "r"(b1));
}

// ---------------- weight prep -------------------------------------------------
__global__ void k_init() {
    int i = blockIdx.x * blockDim.x + threadIdx.x;
    if (i < NG) {
        g_smax[i] = 0xFF800000;
        g_smin[i] = 0x7F800000;
        g_wsum[i] = 0.0f;
    }
    if (i == 0) { g_loss = 0.0; g_acc = 0; }
}

__global__ void k_minmax(const float* __restrict__ scores, const int* __restrict__ qid) {
    int i = blockIdx.x * blockDim.x + threadIdx.x;
    if (i >= BATCH) return;
    int b = __float_as_int(scores[i]);
    int g = qid[i];
    atomicMax(&g_smax[g], b);
    atomicMin(&g_smin[g], b);
}

__global__ void k_weight(const float* __restrict__ scores, const float* __restrict__ ranks,
                         const int* __restrict__ qid) {
    int i = blockIdx.x * blockDim.x + threadIdx.x;
    if (i >= BATCH) return;
    int g = qid[i];
    float w = expf(-0.1f * ranks[i]);
    float mx = __int_as_float(g_smax[g]);
    float mn = __int_as_float(g_smin[g]);
    float den = mx - mn;
    float norm = (den > 0.0f) ? (scores[i] - mn) / den : 0.0f;
    w *= expf(0.01f * norm);
    g_w[i] = w;
    atomicAdd(&g_wsum[g], w);
}

__global__ void k_wnorm(const int* __restrict__ qid) {
    int i = blockIdx.x * blockDim.x + threadIdx.x;
    if (i >= BATCH) return;
    g_w[i] = g_w[i] / g_wsum[qid[i]];
}

// ---------------- fp32 -> fp16 (row-major) ------------------------------------
__global__ void k_convert(const float* __restrict__ Q, const float* __restrict__ A) {
    int idx = blockIdx.x * blockDim.x + threadIdx.x;   // 0 .. 524287
    const float* src = (blockIdx.y == 0) ? Q : A;
    unsigned short* dh = (blockIdx.y == 0) ? g_qh : g_ah;

    size_t e0 = (size_t)idx * 8;
    float4 f0 = *(const float4*)(src + e0);
    float4 f1 = *(const float4*)(src + e0 + 4);
    float v[8] = {f0.x, f0.y, f0.z, f0.w, f1.x, f1.y, f1.z, f1.w};

    unsigned short hs[8];
#pragma unroll
    for (int i = 0; i < 8; i++) {
        hs[i] = __half_as_ushort(__float2half_rn(v[i]));
    }
    uint4 hp;
    hp.x = (unsigned)hs[0] | ((unsigned)hs[1] << 16);
    hp.y = (unsigned)hs[2] | ((unsigned)hs[3] << 16);
    hp.z = (unsigned)hs[4] | ((unsigned)hs[5] << 16);
    hp.w = (unsigned)hs[6] | ((unsigned)hs[7] << 16);
    *(uint4*)(dh + e0) = hp;
}

// ---------------- main: fp16 mma.sync GEMM + fused epilogue -------------------
// Grid (32, 32): CTA tile rows [bx*128,+128) x cols [by*128,+128).
// 8 warps as 4(m) x 2(n); warp tile 32 x 64. BK = 32. 4-stage cp.async pipeline.
// smem: sq[128] int @0, sw[128] float @512, stages @1024: 4 x (2 tiles x 10240B)
#define TILE_B  10240u            // 128 rows x 40 halfs x 2B (stride 80B for LDSM + cp16 align)
#define STG_OFF 1024u
#define STG_SZ  (2u * TILE_B)     // 20480
#define NSTAGE  4
#define SMEM_TOTAL (1024 + NSTAGE * 20480)

__global__ void __launch_bounds__(256) k_mma(const int* __restrict__ qid) {
    extern __shared__ char smem[];
    const unsigned sb = smem_u32(smem);
    const int tid = threadIdx.x;
    const int wid = tid >> 5;
    const int lid = tid & 31;
    const int wm = wid & 3;        // m warp 0..3
    const int wn = wid >> 2;       // n warp 0..1
    const int bx = blockIdx.x, by = blockIdx.y;

    // column tables
    if (tid < 128) {
        int c = by * 128 + tid;
        ((int*)(smem))[tid] = qid[c];
        ((float*)(smem + 512))[tid] = g_w[c];
    }

    float acc[2][8][4];
#pragma unroll
    for (int i = 0; i < 2; i++)
#pragma unroll
        for (int j = 0; j < 8; j++)
#pragma unroll
            for (int k = 0; k < 4; k++) acc[i][j][k] = 0.0f;

    // ---- async load of one k-chunk into stage buf; empty commit past the end
    auto load_chunk = [&](int kc) {
        if (kc < 32) {
            unsigned stg = sb + STG_OFF + (unsigned)(kc & (NSTAGE - 1)) * STG_SZ;
#pragma unroll
            for (int c4 = 0; c4 < 4; c4++) {
                int c = tid + c4 * 256;          // 0..1023
                int tile = c >> 9;               // 0: qh, 1: ah
                int row = (c >> 2) & 127;
                int j = c & 3;
                const unsigned short* base = (tile == 0) ? g_qh : g_ah;
                int grow = ((tile == 0) ? bx : by) * 128 + row;
                const unsigned short* src = base + (size_t)grow * DIM + kc * 32 + 8 * j;
                unsigned dst = stg + tile * TILE_B + row * 80 + 16 * j;
                cp16(dst, src);
            }
        }
        cp_commit();   // constant group count, even past the end
    };

    // A-fragment lane address pieces (row-major m16 x k16 via x4)
    const int a_r = (lid & 15);
    const int a_k = (lid >> 4) << 3;
    // B-fragment lane address pieces (two n8 tiles per x4)
    const int b_n = ((lid >> 4) << 3) + (lid & 7);
    const int b_k = ((lid >> 3) & 1) << 3;

    load_chunk(0);
    load_chunk(1);
    load_chunk(2);

    for (int kc = 0; kc < 32; kc++) {
        cp_wait<2>();         // chunk kc's own stores complete (FIFO: kc+1,kc+2 may pend)
        __syncthreads();      // cross-thread visibility of chunk kc; frees buf (kc+3)%4
        load_chunk(kc + 3);   // prefetch 3 ahead (empty commit past end)

        unsigned stg = sb + STG_OFF + (unsigned)(kc & (NSTAGE - 1)) * STG_SZ;
        unsigned qhb = stg;
        unsigned ahb = stg + TILE_B;

#pragma unroll
        for (int ks = 0; ks < 2; ks++) {
            const int ko = ks * 16;
            unsigned a[2][4], b[4][4];
#pragma unroll
            for (int mt = 0; mt < 2; mt++) {
                unsigned ad = qhb + (wm * 32 + mt * 16 + a_r) * 80 + (ko + a_k) * 2;
                ldsm4(a[mt][0], a[mt][1], a[mt][2], a[mt][3], ad);
            }
#pragma unroll
            for (int p = 0; p < 4; p++) {
                unsigned ad = ahb + (wn * 64 + p * 16 + b_n) * 80 + (ko + b_k) * 2;
                ldsm4(b[p][0], b[p][1], b[p][2], b[p][3], ad);
            }
#pragma unroll
            for (int mt = 0; mt < 2; mt++)
#pragma unroll
                for (int p = 0; p < 4; p++) {
                    mma_f16(acc[mt][2 * p],     a[mt][0], a[mt][1], a[mt][2], a[mt][3], b[p][0], b[p][1]);
                    mma_f16(acc[mt][2 * p + 1], a[mt][0], a[mt][1], a[mt][2], a[mt][3], b[p][2], b[p][3]);
                }
        }
    }

    // ---- fused epilogue -----------------------------------------------------
    const int* sq = (const int*)(smem);
    const float* swt = (const float*)(smem + 512);
    const unsigned fullm = 0xffffffffu;

#pragma unroll
    for (int mt = 0; mt < 2; mt++) {
#pragma unroll
        for (int h = 0; h < 2; h++) {
            int row = bx * 128 + wm * 32 + mt * 16 + h * 8 + (lid >> 2);
            int rq = qid[row];
            float m = -1e30f, s = 0.0f, mv = -1e30f, dot = 0.0f, wr = 0.0f;
            int mj = 0;
#pragma unroll
            for (int nt = 0; nt < 8; nt++) {
#pragma unroll
                for (int b = 0; b < 2; b++) {
                    float val = acc[mt][nt][2 * h + b] * TEMP_INV;
                    int cl = wn * 64 + nt * 8 + 2 * (lid & 3) + b;
                    if (val > m) {
                        s = s * __expf(m - val) + 1.0f;
                        m = val;
                    } else {
                        s += __expf(val - m);
                    }
                    if (val > mv) { mv = val; mj = by * 128 + cl; }
                    if (sq[cl] == rq) {
                        float wj = swt[cl];
                        dot = fmaf(wj, val, dot);
                        wr += wj;
                    }
                }
            }
            // reduce across the 4 lanes owning this row (lanes 4k..4k+3)
#pragma unroll
            for (int off = 2; off > 0; off >>= 1) {
                float om  = __shfl_down_sync(fullm, m, off, 4);
                float os  = __shfl_down_sync(fullm, s, off, 4);
                float omv = __shfl_down_sync(fullm, mv, off, 4);
                int   oj  = __shfl_down_sync(fullm, mj, off, 4);
                float od  = __shfl_down_sync(fullm, dot, off, 4);
                float ow  = __shfl_down_sync(fullm, wr, off, 4);
                float M = fmaxf(m, om);
                s = s * __expf(m - M) + os * __expf(om - M);
                m = M;
                if (omv > mv || (omv == mv && oj < mj)) { mv = omv; mj = oj; }
                dot += od;
                wr += ow;
            }
            if ((lid & 3) == 0) {
                int pidx = row * NSPLIT + (by * 2 + wn);
                g_pm[pidx] = m; g_ps[pidx] = s;
                g_pmaxv[pidx] = mv; g_pmaxj[pidx] = mj;
                g_pdot[pidx] = dot; g_pwr[pidx] = wr;
            }
        }
    }
}

// ---------------- merge splits ------------------------------------------------
__global__ void k_merge(const int* __restrict__ qid) {
    int row = blockIdx.x * blockDim.x + threadIdx.x;
    if (row >= BATCH) return;
    float m = -1e30f, s = 0.0f, mv = -1e30f, dot = 0.0f, wr = 0.0f;
    int mj = 0;
    for (int p = 0; p < NSPLIT; p++) {
        int idx = row * NSPLIT + p;
        float om = g_pm[idx], os = g_ps[idx];
        float M = fmaxf(m, om);
        s = s * __expf(m - M) + os * __expf(om - M);
        m = M;
        float omv = g_pmaxv[idx];
        int oj = g_pmaxj[idx];
        if (omv > mv || (omv == mv && oj < mj)) { mv = omv; mj = oj; }
        dot += g_pdot[idx];
        wr += g_pwr[idx];
    }
    float lse = m + logf(s);
    float per_row = wr * lse - dot;
    int ok = (qid[mj] == qid[row]) ? 1 : 0;
    atomicAdd(&g_loss, (double)per_row);
    atomicAdd(&g_acc, ok);
}

__global__ void k_final(float* __restrict__ out, int out_size) {
    if (threadIdx.x == 0) {
        if (out_size > 0) out[0] = (float)(g_loss / (double)BATCH);
        if (out_size > 1) out[1] = (float)g_acc / (float)BATCH;
    }
}

// ---------------- launch -------------------------------------------------------
extern "C" void kernel_launch(void* const* d_in, const int* in_sizes, int n_in,
                              void* d_out, int out_size) {
    const float* Q      = (const float*)d_in[0];
    const float* A      = (const float*)d_in[1];
    const int*   qid    = (const int*)d_in[2];
    const float* ranks  = (const float*)d_in[3];
    const float* scores = (const float*)d_in[4];
    float* out = (float*)d_out;

    cudaFuncSetAttribute(k_mma, cudaFuncAttributeMaxDynamicSharedMemorySize, SMEM_TOTAL);

    k_init<<<(NG + 255) / 256, 256>>>();
    k_minmax<<<(BATCH + 255) / 256, 256>>>(scores, qid);
    k_weight<<<(BATCH + 255) / 256, 256>>>(scores, ranks, qid);
    k_wnorm<<<(BATCH + 255) / 256, 256>>>(qid);
    k_convert<<<dim3(2048, 2), 256>>>(Q, A);
    k_mma<<<dim3(32, 32), 256, SMEM_TOTAL>>>(qid);
    k_merge<<<(BATCH + 255) / 256, 256>>>(qid);
    k_final<<<1, 32>>>(out, out_size);
}

// round 10
// speedup vs baseline: 4.7250x; 1.1210x over previous
#include <cuda_runtime.h>
#include <cuda_fp16.h>
#include <math.h>

#define BATCH 4096
#define DIM 1024
#define NG 1024
#define NSPLIT 64            // column splits of 64 (per warp-column)
#define TEMP_INV 10.0f

// ---------------- scratch ----------------------------------------------------
__device__ __align__(16) unsigned short g_qh[BATCH * DIM];
__device__ __align__(16) unsigned short g_ah[BATCH * DIM];

__device__ float  g_w[BATCH];
__device__ float  g_pm[BATCH * NSPLIT];
__device__ float  g_ps[BATCH * NSPLIT];
__device__ float  g_pmaxv[BATCH * NSPLIT];
__device__ int    g_pmaxj[BATCH * NSPLIT];
__device__ float  g_pdot[BATCH * NSPLIT];
__device__ float  g_pwr[BATCH * NSPLIT];
__device__ double g_loss;
__device__ int    g_acc;
__device__ unsigned g_ticket;

// ---------------- PTX helpers -------------------------------------------------
__device__ __forceinline__ unsigned smem_u32(const void* p) {
    unsigned a;
    asm("{ .reg .u64 t; cvta.to.shared.u64 t, %1; cvt.u32.u64 %0, t; }" : "=r"(a) : "l"(p));
    return a;
}

__device__ __forceinline__ void cp16(unsigned dst, const void* src) {
    asm volatile("cp.async.cg.shared.global [%0], [%1], 16;" :: "r"(dst), "l"(src) : "memory");
}
__device__ __forceinline__ void cp_commit() {
    asm volatile("cp.async.commit_group;" ::: "memory");
}
template <int N>
__device__ __forceinline__ void cp_wait() {
    asm volatile("cp.async.wait_group %0;" :: "n"(N) : "memory");
}

__device__ __forceinline__ void ldsm4(unsigned& r0, unsigned& r1, unsigned& r2, unsigned& r3,
                                      unsigned addr) {
    asm volatile("ldmatrix.sync.aligned.m8n8.x4.shared.b16 {%0,%1,%2,%3}, [%4];"
        : "=r"(r0), "=r"(r1), "=r"(r2), "=r"(r3) : "r"(addr));
}

__device__ __forceinline__ void mma_f16(float* c, unsigned a0, unsigned a1, unsigned a2,
                                        unsigned a3, unsigned b0, unsigned b1) {
    asm volatile(
        "mma.sync.aligned.m16n8k16.row.col.f32.f16.f16.f32 "
        "{%0,%1,%2,%3}, {%4,%5,%6,%7}, {%8,%9}, {%0,%1,%2,%3};"
        : "+f"(c[0]), "+f"(c[1]), "+f"(c[2]), "+f"(c[3])
        : "r"(a0), "r"(a1), "r"(a2), "r"(a3), "r"(b0), "r"(b1));
}

// ---------------- fused weight prep (single CTA; smem group arrays) -----------
__global__ void __launch_bounds__(1024) k_prep(const float* __restrict__ scores,
                                               const float* __restrict__ ranks,
                                               const int* __restrict__ qid) {
    __shared__ int   smax[NG];
    __shared__ int   smin[NG];
    __shared__ float wsum[NG];
    const int tid = threadIdx.x;

    if (tid < NG) {
        smax[tid] = 0xFF800000;   // -inf bits (scores >= 0 so int order works)
        smin[tid] = 0x7F800000;
        wsum[tid] = 0.0f;
    }
    if (tid == 0) { g_loss = 0.0; g_acc = 0; g_ticket = 0; }
    __syncthreads();

    int   gi[4];
    float sc[4], wv[4];
#pragma unroll
    for (int i = 0; i < 4; i++) {
        int idx = tid + i * 1024;
        gi[i] = qid[idx];
        sc[i] = scores[idx];
        atomicMax(&smax[gi[i]], __float_as_int(sc[i]));
        atomicMin(&smin[gi[i]], __float_as_int(sc[i]));
    }
    __syncthreads();

#pragma unroll
    for (int i = 0; i < 4; i++) {
        int idx = tid + i * 1024;
        float w = expf(-0.1f * ranks[idx]);
        float mx = __int_as_float(smax[gi[i]]);
        float mn = __int_as_float(smin[gi[i]]);
        float den = mx - mn;
        float norm = (den > 0.0f) ? (sc[i] - mn) / den : 0.0f;
        w *= expf(0.01f * norm);
        wv[i] = w;
        atomicAdd(&wsum[gi[i]], w);
    }
    __syncthreads();

#pragma unroll
    for (int i = 0; i < 4; i++) {
        int idx = tid + i * 1024;
        g_w[idx] = wv[i] / wsum[gi[i]];
    }
}

// ---------------- fp32 -> fp16 (row-major) ------------------------------------
__global__ void k_convert(const float* __restrict__ Q, const float* __restrict__ A) {
    int idx = blockIdx.x * blockDim.x + threadIdx.x;   // 0 .. 524287
    const float* src = (blockIdx.y == 0) ? Q : A;
    unsigned short* dh = (blockIdx.y == 0) ? g_qh : g_ah;

    size_t e0 = (size_t)idx * 8;
    float4 f0 = *(const float4*)(src + e0);
    float4 f1 = *(const float4*)(src + e0 + 4);
    float v[8] = {f0.x, f0.y, f0.z, f0.w, f1.x, f1.y, f1.z, f1.w};

    unsigned short hs[8];
#pragma unroll
    for (int i = 0; i < 8; i++) {
        hs[i] = __half_as_ushort(__float2half_rn(v[i]));
    }
    uint4 hp;
    hp.x = (unsigned)hs[0] | ((unsigned)hs[1] << 16);
    hp.y = (unsigned)hs[2] | ((unsigned)hs[3] << 16);
    hp.z = (unsigned)hs[4] | ((unsigned)hs[5] << 16);
    hp.w = (unsigned)hs[6] | ((unsigned)hs[7] << 16);
    *(uint4*)(dh + e0) = hp;
}

// ---------------- main: fp16 mma.sync GEMM + fused epilogue -------------------
// Grid (32, 32): CTA tile rows [bx*128,+128) x cols [by*128,+128).
// 8 warps as 4(m) x 2(n); warp tile 32 x 64. BK = 64, 16 k-iters,
// 3-stage cp.async pipeline (one sync per iter).
// smem: sq[128] int @0, sw[128] float @512, stages @1024: 3 x (2 tiles x 18432B)
#define TILE_B  18432u            // 128 rows x 72 halfs x 2B (144B stride: LDSM conflict-free)
#define STG_OFF 1024u
#define STG_SZ  (2u * TILE_B)     // 36864
#define NSTAGE  3
#define NKIT    16
#define SMEM_TOTAL (1024 + NSTAGE * 36864)

__global__ void __launch_bounds__(256) k_mma(const int* __restrict__ qid) {
    extern __shared__ char smem[];
    const unsigned sb = smem_u32(smem);
    const int tid = threadIdx.x;
    const int wid = tid >> 5;
    const int lid = tid & 31;
    const int wm = wid & 3;        // m warp 0..3
    const int wn = wid >> 2;       // n warp 0..1
    const int bx = blockIdx.x, by = blockIdx.y;

    // column tables
    if (tid < 128) {
        int c = by * 128 + tid;
        ((int*)(smem))[tid] = qid[c];
        ((float*)(smem + 512))[tid] = g_w[c];
    }

    float acc[2][8][4];
#pragma unroll
    for (int i = 0; i < 2; i++)
#pragma unroll
        for (int j = 0; j < 8; j++)
#pragma unroll
            for (int k = 0; k < 4; k++) acc[i][j][k] = 0.0f;

    // ---- async load of one BK=64 chunk (2 tiles x 128 rows x 128B) ----------
    auto load_chunk = [&](int kc) {
        if (kc < NKIT) {
            unsigned stg = sb + STG_OFF + (unsigned)(kc % NSTAGE) * STG_SZ;
#pragma unroll
            for (int c8 = 0; c8 < 8; c8++) {
                int c = tid + c8 * 256;          // 0..2047
                int tile = c >> 10;              // 0: qh, 1: ah
                int ci = c & 1023;
                int row = ci >> 3;
                int j = ci & 7;
                const unsigned short* base = (tile == 0) ? g_qh : g_ah;
                int grow = ((tile == 0) ? bx : by) * 128 + row;
                const unsigned short* src = base + (size_t)grow * DIM + kc * 64 + 8 * j;
                unsigned dst = stg + tile * TILE_B + row * 144 + 16 * j;
                cp16(dst, src);
            }
        }
        cp_commit();   // constant group count, even past the end
    };

    // A-fragment lane address pieces (row-major m16 x k16 via x4)
    const int a_r = (lid & 15);
    const int a_k = (lid >> 4) << 3;
    // B-fragment lane address pieces (two n8 tiles per x4)
    const int b_n = ((lid >> 4) << 3) + (lid & 7);
    const int b_k = ((lid >> 3) & 1) << 3;

    load_chunk(0);
    load_chunk(1);

    for (int kc = 0; kc < NKIT; kc++) {
        cp_wait<1>();         // chunk kc's own stores complete (kc+1 may pend)
        __syncthreads();      // visibility of chunk kc; frees buf (kc+2)%3
        load_chunk(kc + 2);   // prefetch 2 ahead (empty commit past end)

        unsigned stg = sb + STG_OFF + (unsigned)(kc % NSTAGE) * STG_SZ;
        unsigned qhb = stg;
        unsigned ahb = stg + TILE_B;

#pragma unroll
        for (int ks = 0; ks < 4; ks++) {
            const int ko = ks * 16;
            unsigned a[2][4], b[4][4];
#pragma unroll
            for (int mt = 0; mt < 2; mt++) {
                unsigned ad = qhb + (wm * 32 + mt * 16 + a_r) * 144 + (ko + a_k) * 2;
                ldsm4(a[mt][0], a[mt][1], a[mt][2], a[mt][3], ad);
            }
#pragma unroll
            for (int p = 0; p < 4; p++) {
                unsigned ad = ahb + (wn * 64 + p * 16 + b_n) * 144 + (ko + b_k) * 2;
                ldsm4(b[p][0], b[p][1], b[p][2], b[p][3], ad);
            }
#pragma unroll
            for (int mt = 0; mt < 2; mt++)
#pragma unroll
                for (int p = 0; p < 4; p++) {
                    mma_f16(acc[mt][2 * p],     a[mt][0], a[mt][1], a[mt][2], a[mt][3], b[p][0], b[p][1]);
                    mma_f16(acc[mt][2 * p + 1], a[mt][0], a[mt][1], a[mt][2], a[mt][3], b[p][2], b[p][3]);
                }
        }
    }

    // ---- fused epilogue -----------------------------------------------------
    const int* sq = (const int*)(smem);
    const float* swt = (const float*)(smem + 512);
    const unsigned fullm = 0xffffffffu;

#pragma unroll
    for (int mt = 0; mt < 2; mt++) {
#pragma unroll
        for (int h = 0; h < 2; h++) {
            int row = bx * 128 + wm * 32 + mt * 16 + h * 8 + (lid >> 2);
            int rq = qid[row];
            float m = -1e30f, s = 0.0f, mv = -1e30f, dot = 0.0f, wr = 0.0f;
            int mj = 0;
#pragma unroll
            for (int nt = 0; nt < 8; nt++) {
#pragma unroll
                for (int b = 0; b < 2; b++) {
                    float val = acc[mt][nt][2 * h + b] * TEMP_INV;
                    int cl = wn * 64 + nt * 8 + 2 * (lid & 3) + b;
                    if (val > m) {
                        s = s * __expf(m - val) + 1.0f;
                        m = val;
                    } else {
                        s += __expf(val - m);
                    }
                    if (val > mv) { mv = val; mj = by * 128 + cl; }
                    if (sq[cl] == rq) {
                        float wj = swt[cl];
                        dot = fmaf(wj, val, dot);
                        wr += wj;
                    }
                }
            }
            // reduce across the 4 lanes owning this row (lanes 4k..4k+3)
#pragma unroll
            for (int off = 2; off > 0; off >>= 1) {
                float om  = __shfl_down_sync(fullm, m, off, 4);
                float os  = __shfl_down_sync(fullm, s, off, 4);
                float omv = __shfl_down_sync(fullm, mv, off, 4);
                int   oj  = __shfl_down_sync(fullm, mj, off, 4);
                float od  = __shfl_down_sync(fullm, dot, off, 4);
                float ow  = __shfl_down_sync(fullm, wr, off, 4);
                float M = fmaxf(m, om);
                s = s * __expf(m - M) + os * __expf(om - M);
                m = M;
                if (omv > mv || (omv == mv && oj < mj)) { mv = omv; mj = oj; }
                dot += od;
                wr += ow;
            }
            if ((lid & 3) == 0) {
                int pidx = row * NSPLIT + (by * 2 + wn);
                g_pm[pidx] = m; g_ps[pidx] = s;
                g_pmaxv[pidx] = mv; g_pmaxj[pidx] = mj;
                g_pdot[pidx] = dot; g_pwr[pidx] = wr;
            }
        }
    }
}

// ---------------- merge splits + finalize (last block writes out) -------------
__global__ void k_merge(const int* __restrict__ qid, float* __restrict__ out, int out_size) {
    __shared__ double lred[8];
    __shared__ int    ared[8];
    __shared__ unsigned done;
    int row = blockIdx.x * blockDim.x + threadIdx.x;
    const int tid = threadIdx.x;

    float m = -1e30f, s = 0.0f, mv = -1e30f, dot = 0.0f, wr = 0.0f;
    int mj = 0;
    for (int p = 0; p < NSPLIT; p++) {
        int idx = row * NSPLIT + p;
        float om = g_pm[idx], os = g_ps[idx];
        float M = fmaxf(m, om);
        s = s * __expf(m - M) + os * __expf(om - M);
        m = M;
        float omv = g_pmaxv[idx];
        int oj = g_pmaxj[idx];
        if (omv > mv || (omv == mv && oj < mj)) { mv = omv; mj = oj; }
        dot += g_pdot[idx];
        wr += g_pwr[idx];
    }
    float lse = m + logf(s);
    double per_row = (double)(wr * lse - dot);
    int ok = (qid[mj] == qid[row]) ? 1 : 0;

    // block reduction
    const unsigned fullm = 0xffffffffu;
#pragma unroll
    for (int off = 16; off > 0; off >>= 1) {
        per_row += __shfl_down_sync(fullm, per_row, off);
        ok += __shfl_down_sync(fullm, ok, off);
    }
    if ((tid & 31) == 0) { lred[tid >> 5] = per_row; ared[tid >> 5] = ok; }
    __syncthreads();
    if (tid == 0) {
        double lsum = 0.0; int asum = 0;
#pragma unroll
        for (int i = 0; i < 8; i++) { lsum += lred[i]; asum += ared[i]; }
        atomicAdd(&g_loss, lsum);
        atomicAdd(&g_acc, asum);
        __threadfence();
        done = atomicAdd(&g_ticket, 1u);
    }
    __syncthreads();
    if (done == gridDim.x - 1) {   // last block to finish
        if (tid == 0) {
            if (out_size > 0) out[0] = (float)(g_loss / (double)BATCH);
            if (out_size > 1) out[1] = (float)g_acc / (float)BATCH;
        }
    }
}

// ---------------- launch -------------------------------------------------------
extern "C" void kernel_launch(void* const* d_in, const int* in_sizes, int n_in,
                              void* d_out, int out_size) {
    const float* Q      = (const float*)d_in[0];
    const float* A      = (const float*)d_in[1];
    const int*   qid    = (const int*)d_in[2];
    const float* ranks  = (const float*)d_in[3];
    const float* scores = (const float*)d_in[4];
    float* out = (float*)d_out;

    cudaFuncSetAttribute(k_mma, cudaFuncAttributeMaxDynamicSharedMemorySize, SMEM_TOTAL);

    k_prep<<<1, 1024>>>(scores, ranks, qid);
    k_convert<<<dim3(2048, 2), 256>>>(Q, A);
    k_mma<<<dim3(32, 32), 256, SMEM_TOTAL>>>(qid);
    k_merge<<<16, 256>>>(qid, out, out_size);
}

// round 11
// speedup vs baseline: 6.4638x; 1.3680x over previous
#include <cuda_runtime.h>
#include <cuda_fp16.h>
#include <math.h>

#define BATCH 4096
#define DIM 1024
#define NG 1024
#define NSPLIT 64            // column splits of 64 (per warp-column)
#define TEMP_INV 10.0f

// ---------------- scratch ----------------------------------------------------
__device__ __align__(16) unsigned short g_qh[BATCH * DIM];
__device__ __align__(16) unsigned short g_ah[BATCH * DIM];

__device__ float  g_w[BATCH];
__device__ float  g_pm[BATCH * NSPLIT];
__device__ float  g_ps[BATCH * NSPLIT];
__device__ float  g_pmaxv[BATCH * NSPLIT];
__device__ int    g_pmaxj[BATCH * NSPLIT];
__device__ float  g_pdot[BATCH * NSPLIT];
__device__ float  g_pwr[BATCH * NSPLIT];
__device__ double g_loss;
__device__ int    g_acc;
__device__ unsigned g_ticket;

// ---------------- PTX helpers -------------------------------------------------
__device__ __forceinline__ unsigned smem_u32(const void* p) {
    unsigned a;
    asm("{ .reg .u64 t; cvta.to.shared.u64 t, %1; cvt.u32.u64 %0, t; }" : "=r"(a) : "l"(p));
    return a;
}

__device__ __forceinline__ void cp16(unsigned dst, const void* src) {
    asm volatile("cp.async.cg.shared.global [%0], [%1], 16;" :: "r"(dst), "l"(src) : "memory");
}
__device__ __forceinline__ void cp_commit() {
    asm volatile("cp.async.commit_group;" ::: "memory");
}
template <int N>
__device__ __forceinline__ void cp_wait() {
    asm volatile("cp.async.wait_group %0;" :: "n"(N) : "memory");
}

__device__ __forceinline__ void ldsm4(unsigned& r0, unsigned& r1, unsigned& r2, unsigned& r3,
                                      unsigned addr) {
    asm volatile("ldmatrix.sync.aligned.m8n8.x4.shared.b16 {%0,%1,%2,%3}, [%4];"
        : "=r"(r0), "=r"(r1), "=r"(r2), "=r"(r3) : "r"(addr));
}

__device__ __forceinline__ void mma_f16(float* c, unsigned a0, unsigned a1, unsigned a2,
                                        unsigned a3, unsigned b0, unsigned b1) {
    asm volatile(
        "mma.sync.aligned.m16n8k16.row.col.f32.f16.f16.f32 "
        "{%0,%1,%2,%3}, {%4,%5,%6,%7}, {%8,%9}, {%0,%1,%2,%3};"
        : "+f"(c[0]), "+f"(c[1]), "+f"(c[2]), "+f"(c[3])
        : "r"(a0), "r"(a1), "r"(a2), "r"(a3), "r"(b0), "r"(b1));
}

// ---------------- fused weight prep (single CTA; smem group arrays) -----------
__global__ void __launch_bounds__(1024) k_prep(const float* __restrict__ scores,
                                               const float* __restrict__ ranks,
                                               const int* __restrict__ qid) {
    __shared__ int   smax[NG];
    __shared__ int   smin[NG];
    __shared__ float wsum[NG];
    const int tid = threadIdx.x;

    if (tid < NG) {
        smax[tid] = 0xFF800000;   // -inf bits (scores >= 0 so int order works)
        smin[tid] = 0x7F800000;
        wsum[tid] = 0.0f;
    }
    if (tid == 0) { g_loss = 0.0; g_acc = 0; g_ticket = 0; }
    __syncthreads();

    int   gi[4];
    float sc[4], wv[4];
#pragma unroll
    for (int i = 0; i < 4; i++) {
        int idx = tid + i * 1024;
        gi[i] = qid[idx];
        sc[i] = scores[idx];
        atomicMax(&smax[gi[i]], __float_as_int(sc[i]));
        atomicMin(&smin[gi[i]], __float_as_int(sc[i]));
    }
    __syncthreads();

#pragma unroll
    for (int i = 0; i < 4; i++) {
        int idx = tid + i * 1024;
        float w = expf(-0.1f * ranks[idx]);
        float mx = __int_as_float(smax[gi[i]]);
        float mn = __int_as_float(smin[gi[i]]);
        float den = mx - mn;
        float norm = (den > 0.0f) ? (sc[i] - mn) / den : 0.0f;
        w *= expf(0.01f * norm);
        wv[i] = w;
        atomicAdd(&wsum[gi[i]], w);
    }
    __syncthreads();

#pragma unroll
    for (int i = 0; i < 4; i++) {
        int idx = tid + i * 1024;
        g_w[idx] = wv[i] / wsum[gi[i]];
    }
}

// ---------------- fp32 -> fp16 (row-major) ------------------------------------
__global__ void k_convert(const float* __restrict__ Q, const float* __restrict__ A) {
    int idx = blockIdx.x * blockDim.x + threadIdx.x;   // 0 .. 524287
    const float* src = (blockIdx.y == 0) ? Q : A;
    unsigned short* dh = (blockIdx.y == 0) ? g_qh : g_ah;

    size_t e0 = (size_t)idx * 8;
    float4 f0 = *(const float4*)(src + e0);
    float4 f1 = *(const float4*)(src + e0 + 4);
    float v[8] = {f0.x, f0.y, f0.z, f0.w, f1.x, f1.y, f1.z, f1.w};

    unsigned short hs[8];
#pragma unroll
    for (int i = 0; i < 8; i++) {
        hs[i] = __half_as_ushort(__float2half_rn(v[i]));
    }
    uint4 hp;
    hp.x = (unsigned)hs[0] | ((unsigned)hs[1] << 16);
    hp.y = (unsigned)hs[2] | ((unsigned)hs[3] << 16);
    hp.z = (unsigned)hs[4] | ((unsigned)hs[5] << 16);
    hp.w = (unsigned)hs[6] | ((unsigned)hs[7] << 16);
    *(uint4*)(dh + e0) = hp;
}

// ---------------- main: fp16 mma.sync GEMM + fused epilogue -------------------
// Grid (32, 32): CTA tile rows [bx*128,+128) x cols [by*128,+128).
// 8 warps as 4(m) x 2(n); warp tile 32 x 64. BK = 64, 16 k-iters,
// 3-stage cp.async pipeline (one sync per iter).
// smem: sq[128] int @0, sw[128] float @512, stages @1024: 3 x (2 tiles x 18432B)
#define TILE_B  18432u            // 128 rows x 72 halfs x 2B (144B stride: LDSM conflict-free)
#define STG_OFF 1024u
#define STG_SZ  (2u * TILE_B)     // 36864
#define NSTAGE  3
#define NKIT    16
#define SMEM_TOTAL (1024 + NSTAGE * 36864)

__global__ void __launch_bounds__(256) k_mma(const int* __restrict__ qid) {
    extern __shared__ char smem[];
    const unsigned sb = smem_u32(smem);
    const int tid = threadIdx.x;
    const int wid = tid >> 5;
    const int lid = tid & 31;
    const int wm = wid & 3;        // m warp 0..3
    const int wn = wid >> 2;       // n warp 0..1
    const int bx = blockIdx.x, by = blockIdx.y;

    // column tables
    if (tid < 128) {
        int c = by * 128 + tid;
        ((int*)(smem))[tid] = qid[c];
        ((float*)(smem + 512))[tid] = g_w[c];
    }

    float acc[2][8][4];
#pragma unroll
    for (int i = 0; i < 2; i++)
#pragma unroll
        for (int j = 0; j < 8; j++)
#pragma unroll
            for (int k = 0; k < 4; k++) acc[i][j][k] = 0.0f;

    // ---- async load of one BK=64 chunk (2 tiles x 128 rows x 128B) ----------
    auto load_chunk = [&](int kc) {
        if (kc < NKIT) {
            unsigned stg = sb + STG_OFF + (unsigned)(kc % NSTAGE) * STG_SZ;
#pragma unroll
            for (int c8 = 0; c8 < 8; c8++) {
                int c = tid + c8 * 256;          // 0..2047
                int tile = c >> 10;              // 0: qh, 1: ah
                int ci = c & 1023;
                int row = ci >> 3;
                int j = ci & 7;
                const unsigned short* base = (tile == 0) ? g_qh : g_ah;
                int grow = ((tile == 0) ? bx : by) * 128 + row;
                const unsigned short* src = base + (size_t)grow * DIM + kc * 64 + 8 * j;
                unsigned dst = stg + tile * TILE_B + row * 144 + 16 * j;
                cp16(dst, src);
            }
        }
        cp_commit();   // constant group count, even past the end
    };

    // A-fragment lane address pieces (row-major m16 x k16 via x4)
    const int a_r = (lid & 15);
    const int a_k = (lid >> 4) << 3;
    // B-fragment lane address pieces (two n8 tiles per x4)
    const int b_n = ((lid >> 4) << 3) + (lid & 7);
    const int b_k = ((lid >> 3) & 1) << 3;

    load_chunk(0);
    load_chunk(1);

    for (int kc = 0; kc < NKIT; kc++) {
        cp_wait<1>();         // chunk kc's own stores complete (kc+1 may pend)
        __syncthreads();      // visibility of chunk kc; frees buf (kc+2)%3
        load_chunk(kc + 2);   // prefetch 2 ahead (empty commit past end)

        unsigned stg = sb + STG_OFF + (unsigned)(kc % NSTAGE) * STG_SZ;
        unsigned qhb = stg;
        unsigned ahb = stg + TILE_B;

#pragma unroll
        for (int ks = 0; ks < 4; ks++) {
            const int ko = ks * 16;
            unsigned a[2][4], b[4][4];
#pragma unroll
            for (int mt = 0; mt < 2; mt++) {
                unsigned ad = qhb + (wm * 32 + mt * 16 + a_r) * 144 + (ko + a_k) * 2;
                ldsm4(a[mt][0], a[mt][1], a[mt][2], a[mt][3], ad);
            }
#pragma unroll
            for (int p = 0; p < 4; p++) {
                unsigned ad = ahb + (wn * 64 + p * 16 + b_n) * 144 + (ko + b_k) * 2;
                ldsm4(b[p][0], b[p][1], b[p][2], b[p][3], ad);
            }
#pragma unroll
            for (int mt = 0; mt < 2; mt++)
#pragma unroll
                for (int p = 0; p < 4; p++) {
                    mma_f16(acc[mt][2 * p],     a[mt][0], a[mt][1], a[mt][2], a[mt][3], b[p][0], b[p][1]);
                    mma_f16(acc[mt][2 * p + 1], a[mt][0], a[mt][1], a[mt][2], a[mt][3], b[p][2], b[p][3]);
                }
        }
    }

    // ---- fused epilogue -----------------------------------------------------
    const int* sq = (const int*)(smem);
    const float* swt = (const float*)(smem + 512);
    const unsigned fullm = 0xffffffffu;

#pragma unroll
    for (int mt = 0; mt < 2; mt++) {
#pragma unroll
        for (int h = 0; h < 2; h++) {
            int row = bx * 128 + wm * 32 + mt * 16 + h * 8 + (lid >> 2);
            int rq = qid[row];
            float m = -1e30f, s = 0.0f, mv = -1e30f, dot = 0.0f, wr = 0.0f;
            int mj = 0;
#pragma unroll
            for (int nt = 0; nt < 8; nt++) {
#pragma unroll
                for (int b = 0; b < 2; b++) {
                    float val = acc[mt][nt][2 * h + b] * TEMP_INV;
                    int cl = wn * 64 + nt * 8 + 2 * (lid & 3) + b;
                    if (val > m) {
                        s = s * __expf(m - val) + 1.0f;
                        m = val;
                    } else {
                        s += __expf(val - m);
                    }
                    if (val > mv) { mv = val; mj = by * 128 + cl; }
                    if (sq[cl] == rq) {
                        float wj = swt[cl];
                        dot = fmaf(wj, val, dot);
                        wr += wj;
                    }
                }
            }
            // reduce across the 4 lanes owning this row (lanes 4k..4k+3)
#pragma unroll
            for (int off = 2; off > 0; off >>= 1) {
                float om  = __shfl_down_sync(fullm, m, off, 4);
                float os  = __shfl_down_sync(fullm, s, off, 4);
                float omv = __shfl_down_sync(fullm, mv, off, 4);
                int   oj  = __shfl_down_sync(fullm, mj, off, 4);
                float od  = __shfl_down_sync(fullm, dot, off, 4);
                float ow  = __shfl_down_sync(fullm, wr, off, 4);
                float M = fmaxf(m, om);
                s = s * __expf(m - M) + os * __expf(om - M);
                m = M;
                if (omv > mv || (omv == mv && oj < mj)) { mv = omv; mj = oj; }
                dot += od;
                wr += ow;
            }
            if ((lid & 3) == 0) {
                int pidx = row * NSPLIT + (by * 2 + wn);
                g_pm[pidx] = m; g_ps[pidx] = s;
                g_pmaxv[pidx] = mv; g_pmaxj[pidx] = mj;
                g_pdot[pidx] = dot; g_pwr[pidx] = wr;
            }
        }
    }
}

// ---------------- merge: one warp per row (coalesced) + finalize --------------
// Grid: 256 blocks x 256 threads = 4096 warps... (8 warps/block, 1 row/warp).
__global__ void __launch_bounds__(256) k_merge(const int* __restrict__ qid,
                                               float* __restrict__ out, int out_size) {
    __shared__ double lred[8];
    __shared__ int    ared[8];
    __shared__ unsigned done;
    const int tid = threadIdx.x;
    const int lid = tid & 31;
    const int row = blockIdx.x * 8 + (tid >> 5);
    const unsigned fullm = 0xffffffffu;

    // lane handles splits 2*lid and 2*lid+1 (coalesced across the warp)
    int i0 = row * NSPLIT + 2 * lid;
    float m0 = g_pm[i0],     s0 = g_ps[i0];
    float m1 = g_pm[i0 + 1], s1 = g_ps[i0 + 1];
    float v0 = g_pmaxv[i0],  v1 = g_pmaxv[i0 + 1];
    int   j0 = g_pmaxj[i0],  j1 = g_pmaxj[i0 + 1];
    float dot = g_pdot[i0] + g_pdot[i0 + 1];
    float wr  = g_pwr[i0] + g_pwr[i0 + 1];

    float m = fmaxf(m0, m1);
    float s = s0 * __expf(m0 - m) + s1 * __expf(m1 - m);
    float mv = v0; int mj = j0;
    if (v1 > mv || (v1 == mv && j1 < mj)) { mv = v1; mj = j1; }

    // 32-lane butterfly reduce (all ops associative+commutative)
#pragma unroll
    for (int off = 16; off > 0; off >>= 1) {
        float om  = __shfl_xor_sync(fullm, m, off);
        float os  = __shfl_xor_sync(fullm, s, off);
        float omv = __shfl_xor_sync(fullm, mv, off);
        int   oj  = __shfl_xor_sync(fullm, mj, off);
        float od  = __shfl_xor_sync(fullm, dot, off);
        float ow  = __shfl_xor_sync(fullm, wr, off);
        float M = fmaxf(m, om);
        s = s * __expf(m - M) + os * __expf(om - M);
        m = M;
        if (omv > mv || (omv == mv && oj < mj)) { mv = omv; mj = oj; }
        dot += od;
        wr += ow;
    }

    double per_row = 0.0;
    int ok = 0;
    if (lid == 0) {
        float lse = m + logf(s);
        per_row = (double)(wr * lse - dot);
        ok = (qid[mj] == qid[row]) ? 1 : 0;
        lred[tid >> 5] = per_row;
        ared[tid >> 5] = ok;
    }
    __syncthreads();
    if (tid == 0) {
        double lsum = 0.0; int asum = 0;
#pragma unroll
        for (int i = 0; i < 8; i++) { lsum += lred[i]; asum += ared[i]; }
        atomicAdd(&g_loss, lsum);
        atomicAdd(&g_acc, asum);
        __threadfence();
        done = atomicAdd(&g_ticket, 1u);
    }
    __syncthreads();
    if (done == gridDim.x - 1) {   // last block to finish
        if (tid == 0) {
            if (out_size > 0) out[0] = (float)(g_loss / (double)BATCH);
            if (out_size > 1) out[1] = (float)g_acc / (float)BATCH;
        }
    }
}

// ---------------- launch -------------------------------------------------------
extern "C" void kernel_launch(void* const* d_in, const int* in_sizes, int n_in,
                              void* d_out, int out_size) {
    const float* Q      = (const float*)d_in[0];
    const float* A      = (const float*)d_in[1];
    const int*   qid    = (const int*)d_in[2];
    const float* ranks  = (const float*)d_in[3];
    const float* scores = (const float*)d_in[4];
    float* out = (float*)d_out;

    cudaFuncSetAttribute(k_mma, cudaFuncAttributeMaxDynamicSharedMemorySize, SMEM_TOTAL);

    k_prep<<<1, 1024>>>(scores, ranks, qid);
    k_convert<<<dim3(2048, 2), 256>>>(Q, A);
    k_mma<<<dim3(32, 32), 256, SMEM_TOTAL>>>(qid);
    k_merge<<<512, 256>>>(qid, out, out_size);
}